// round 14
// baseline (speedup 1.0000x reference)
#include <cuda_runtime.h>
#include <cstdint>

#define OMEGA 30.0f
#define HID 128
#define MROW 128          // points per CTA
#define THREADS 512
#define NPTS 2048
#define NCHUNK (NPTS / MROW)
#define SW 132            // row stride in words for hP / WT (conflict-tuned)

// smem offsets (floats)
#define HP_SZ   (MROW * SW)              // 16896
#define WT_OFF  HP_SZ
#define WT_SZ   (HID * SW)               // 16896
#define CS_OFF  (WT_OFF + WT_SZ)
#define BIAS_OFF (CS_OFF + 1024)
#define ZWB_OFF (BIAS_OFF + 128)
#define W3_OFF  (ZWB_OFF + 128)
#define PART_OFF (W3_OFF + 128)
#define ZSM_OFF (PART_OFF + 512)
#define B3_OFF  (ZSM_OFF + 16)
#define SMEM_FLOATS (B3_OFF + 8)
#define SMEM_BYTES  (SMEM_FLOATS * 4)

// ---------------- packed f32x2 helpers ----------------
__device__ __forceinline__ uint64_t pack2(float lo, float hi) {
    uint64_t r;
    asm("mov.b64 %0, {%1, %2};" : "=l"(r) : "f"(lo), "f"(hi));
    return r;
}
__device__ __forceinline__ float2 unpack2(uint64_t v) {
    float2 f;
    asm("mov.b64 {%0, %1}, %2;" : "=f"(f.x), "=f"(f.y) : "l"(v));
    return f;
}
__device__ __forceinline__ uint64_t fma2(uint64_t a, uint64_t b, uint64_t c) {
    uint64_t d;
    asm("fma.rn.f32x2 %0, %1, %2, %3;" : "=l"(d) : "l"(a), "l"(b), "l"(c));
    return d;
}
__device__ __forceinline__ uint64_t add2(uint64_t a, uint64_t b) {
    uint64_t d;
    asm("add.rn.f32x2 %0, %1, %2;" : "=l"(d) : "l"(a), "l"(b));
    return d;
}
#define DUP(c) pack2((c), (c))

// -------- packed sin via exact CW reduction + MUFU poly (both lanes) --------
__device__ __forceinline__ uint64_t sin2(uint64_t x2) {
    uint64_t y2 = fma2(x2, DUP(0.3183098861837907f), DUP(12582912.0f));
    uint64_t sgn = (y2 & 0x0000000100000001ULL) << 31;
    uint64_t k2 = add2(y2, DUP(-12582912.0f));
    uint64_t r2 = fma2(k2, DUP(-3.14159274f), x2);
    r2 = fma2(k2, DUP(8.742277657e-8f), r2);
    r2 ^= sgn;                       // sin(x) = sin((-1)^k r)
    float2 rf = unpack2(r2);
    return pack2(__sinf(rf.x), __sinf(rf.y));
}

// ------------- one layer, k-pair packed: h' = sin(OMEGA*hP@W + biasO) -------
// hP[p][k] point-major (stride SW), WT[c][k] col-major (stride SW).
// Thread tile: 4 points {p0+8j} x 8 cols {c0+16t}. Each fma2 = 2 k-steps.
// biasO pre-scaled by OMEGA (layer0: carries the folded latent term).
// PF=1: prefetch + transpose-dequant NEXT layer into WT + bias_slot after the
// internal sync (overlapped with writeback). Caller syncs after return.
template<int K, int PF>
__device__ __forceinline__ void layer_gemm_sin(float* hP, float* WT,
                                               const float* biasO,
                                               int p0, int c0,
                                               const int* nlab,
                                               const float* ncent,
                                               const float* nbias,
                                               float* bias_slot, int tid) {
    uint64_t acc[4][8];
#pragma unroll
    for (int j = 0; j < 4; j++)
#pragma unroll
        for (int t = 0; t < 8; t++) acc[j][t] = 0ULL;

#pragma unroll 4
    for (int kk = 0; kk < K; kk += 2) {
        uint64_t A[4], Bv[8];
#pragma unroll
        for (int j = 0; j < 4; j++)
            A[j] = *(const uint64_t*)(hP + (p0 + 8 * j) * SW + kk);
#pragma unroll
        for (int t = 0; t < 8; t++)
            Bv[t] = *(const uint64_t*)(WT + (c0 + 16 * t) * SW + kk);
#pragma unroll
        for (int j = 0; j < 4; j++) {
            uint64_t a = A[j];
#pragma unroll
            for (int t = 0; t < 8; t++)
                acc[j][t] = fma2(a, Bv[t], acc[j][t]);
        }
    }

    // epilogue: horizontal add, x = OMEGA*s + biasO, packed sin
    float bv[8];
#pragma unroll
    for (int t = 0; t < 8; t++) bv[t] = biasO[c0 + 16 * t];
    float res[4][8];
#pragma unroll
    for (int j = 0; j < 4; j++)
#pragma unroll
        for (int t = 0; t < 8; t++) {
            float2 f = unpack2(acc[j][t]);
            res[j][t] = fmaf(OMEGA, f.x + f.y, bv[t]);
        }
#pragma unroll
    for (int j = 0; j < 4; j++)
#pragma unroll
        for (int t = 0; t < 8; t += 2) {
            float2 f = unpack2(sin2(pack2(res[j][t], res[j][t + 1])));
            res[j][t] = f.x; res[j][t + 1] = f.y;
        }
    __syncthreads();   // all reads of hP/WT/biasO complete

    // PF: issue label LDGs early (hide behind writeback)
    int vlab[32];
    float nb = 0.0f;
    int pc = 0, pkq = 0;
    if (PF) {
        pc = tid >> 2; pkq = tid & 3;
        const int* lp = nlab + (pkq * 32) * HID + pc;
#pragma unroll
        for (int i = 0; i < 32; i++) vlab[i] = lp[i * HID];
        if (tid < HID) nb = nbias[tid];
    }

    // writeback: scattered STS.32, bank = lane + const (conflict-free)
#pragma unroll
    for (int j = 0; j < 4; j++) {
        float* row = hP + (p0 + 8 * j) * SW;
#pragma unroll
        for (int t = 0; t < 8; t++) row[c0 + 16 * t] = res[j][t];
    }

    if (PF) {
        float* wrow = WT + pc * SW + pkq * 32;
#pragma unroll
        for (int g = 0; g < 8; g++) {
            float4 w;
            w.x = ncent[vlab[4 * g]];     w.y = ncent[vlab[4 * g + 1]];
            w.z = ncent[vlab[4 * g + 2]]; w.w = ncent[vlab[4 * g + 3]];
            *(float4*)(wrow + 4 * g) = w;
        }
        if (tid < HID) bias_slot[tid] = OMEGA * nb;
    }
}

__global__ void __launch_bounds__(THREADS, 1)
ecnr_kernel(const float* __restrict__ x,
            const int* __restrict__ mlp_idx,
            const int* __restrict__ block_idx,
            const float* __restrict__ latent_table,
            const float* __restrict__ cent0, const int* __restrict__ lab0, const float* __restrict__ bias0,
            const float* __restrict__ cent1, const int* __restrict__ lab1, const float* __restrict__ bias1,
            const float* __restrict__ cent2, const int* __restrict__ lab2, const float* __restrict__ bias2,
            const float* __restrict__ cent3, const int* __restrict__ lab3, const float* __restrict__ bias3,
            float* __restrict__ out) {
    extern __shared__ float sm[];
    float* hP  = sm;                    // [128][SW]
    float* WT  = sm + WT_OFF;           // [128][SW]
    float* cs0 = sm + CS_OFF;
    float* cs1 = cs0 + 256;
    float* cs2 = cs1 + 256;
    float* cs3 = cs2 + 256;
    float* bias_s = sm + BIAS_OFF;      // 128 (OMEGA*bias, layers 1-2)
    float* zwb  = sm + ZWB_OFF;         // 128
    float* w3s  = sm + W3_OFF;          // 128
    float* part = sm + PART_OFF;        // 512
    float* zsm  = sm + ZSM_OFF;         // 13
    float* b3s  = sm + B3_OFF;          // 1

    int tid = threadIdx.x;
    int b   = blockIdx.y;
    int pt0 = blockIdx.x * MROW;
    int mlp = mlp_idx[b];
    int blk = block_idx[b];

    if (tid < 256) {
        cs0[tid] = cent0[tid];
        cs1[tid] = cent1[tid];
        cs2[tid] = cent2[tid];
        cs3[tid] = cent3[tid];
    }
    if (tid == 0) b3s[0] = bias3[mlp];
    if (tid < 13) zsm[tid] = latent_table[((long)mlp * 8 + blk) * 13 + tid];

    // layer-0 input: hP[p][0..3] = (x, y, z, 0)
    if (tid < MROW) {
        const float* xp = x + ((long)b * NPTS + pt0 + tid) * 3;
        float4 h4 = make_float4(xp[0], xp[1], xp[2], 0.0f);
        *(float4*)(hP + tid * SW) = h4;
    }

    // layer-0 labels (all 16 k-rows for this thread's column), bias0
    int v0[16];
    float bia0 = 0.0f;
    if (tid < HID) {
        const int* lp = lab0 + mlp * (16 * HID) + tid;
#pragma unroll
        for (int i = 0; i < 16; i++) v0[i] = lp[i * HID];
        bia0 = bias0[mlp * HID + tid];
    }
    __syncthreads();        // cs0/zsm/hP visible

    // WT0[c][0..3] = (W0,W1,W2,0); zwb = OMEGA*(z.W[3:16] + b0)
    if (tid < HID) {
        float4 w = make_float4(cs0[v0[0]], cs0[v0[1]], cs0[v0[2]], 0.0f);
        *(float4*)(WT + tid * SW) = w;
        float s = bia0;
#pragma unroll
        for (int j = 0; j < 13; j++)
            s = fmaf(zsm[j], cs0[v0[3 + j]], s);
        zwb[tid] = OMEGA * s;
    }
    __syncthreads();

    // tiling: 4 points {p0+8j}, 8 cols {c0+16t}
    int wid = tid >> 5, lane = tid & 31;
    int p0 = (wid >> 2) * 32 + (lane >> 2);
    int c0 = (wid & 3) * 4 + (lane & 3);

    layer_gemm_sin<4, 1>(hP, WT, zwb, p0, c0,
                         lab1 + (long)mlp * (HID * HID), cs1,
                         bias1 + mlp * HID, bias_s, tid);
    __syncthreads();

    layer_gemm_sin<128, 1>(hP, WT, bias_s, p0, c0,
                           lab2 + (long)mlp * (HID * HID), cs2,
                           bias2 + mlp * HID, bias_s, tid);
    __syncthreads();

    layer_gemm_sin<128, 0>(hP, WT, bias_s, p0, c0,
                           nullptr, nullptr, nullptr, nullptr, tid);

    // layer-3 weights (128x1)
    if (tid < 32) {
        int4 v = ((const int4*)(lab3 + mlp * HID))[tid];
        float4 w = make_float4(cs3[v.x], cs3[v.y], cs3[v.z], cs3[v.w]);
        ((float4*)w3s)[tid] = w;
    }
    __syncthreads();

    // layer 3: packed dot, 4 threads per point (k-quarters)
    {
        int p = tid >> 2, q = tid & 3;
        const float* hp = hP + p * SW + q * 32;
        const float* wp = w3s + q * 32;
        uint64_t s2 = 0ULL;
#pragma unroll 8
        for (int i = 0; i < 16; i++)
            s2 = fma2(*(const uint64_t*)(hp + 2 * i),
                      *(const uint64_t*)(wp + 2 * i), s2);
        float2 f = unpack2(s2);
        part[q * MROW + p] = f.x + f.y;
    }
    __syncthreads();
    if (tid < MROW) {
        out[(long)b * NPTS + pt0 + tid] =
            part[tid] + part[128 + tid] + part[256 + tid] + part[384 + tid] + b3s[0];
    }
}

extern "C" void kernel_launch(void* const* d_in, const int* in_sizes, int n_in,
                              void* d_out, int out_size) {
    (void)n_in; (void)out_size;
    cudaFuncSetAttribute(ecnr_kernel,
                         cudaFuncAttributeMaxDynamicSharedMemorySize, SMEM_BYTES);
    int B = in_sizes[1];                 // number of samples (mlp_idx count)
    dim3 grid(NCHUNK, B);
    ecnr_kernel<<<grid, THREADS, SMEM_BYTES>>>(
        (const float*)d_in[0], (const int*)d_in[1], (const int*)d_in[2],
        (const float*)d_in[3],
        (const float*)d_in[4],  (const int*)d_in[5],  (const float*)d_in[6],
        (const float*)d_in[7],  (const int*)d_in[8],  (const float*)d_in[9],
        (const float*)d_in[10], (const int*)d_in[11], (const float*)d_in[12],
        (const float*)d_in[13], (const int*)d_in[14], (const float*)d_in[15],
        (float*)d_out);
}